// round 14
// baseline (speedup 1.0000x reference)
#include <cuda_runtime.h>
#include <cstdint>

#define TAGS 2048
#define NCTA 128
#define ROWS 16          // NCTA*ROWS == TAGS
#define NTHR 256
#define NEGV -10000.0f

// p = exp(fv - sigma) published as bf16 pairs (u32 per 2 tags), dbl-buffered.
__device__ unsigned g_p[2][TAGS / 2];
__device__ float    g_V[2][8 * 32];       // sigma source value, 8 replicas x 128B
__device__ unsigned g_bar;                // grid barrier counter (R3-proven)

__global__ void init_kernel() {
    int j = blockIdx.x * blockDim.x + threadIdx.x;
    if (j < TAGS / 2) {
        g_p[0][j] = (j == 0) ? 0x00003F80u : 0u;   // {bf16(1)@lo=col0, bf16(0)@hi=col1}
        g_p[1][j] = 0u;
    }
    if (j < 8) { g_V[0][j * 32] = 0.0f; g_V[1][j * 32] = 0.0f; }
    if (j == 0) g_bar = 0u;
}

__device__ __forceinline__ float bflo(unsigned u) { return __uint_as_float(u << 16); }
__device__ __forceinline__ float bfhi(unsigned u) { return __uint_as_float(u & 0xFFFF0000u); }
// pack: a -> low half (even col), b -> high half (odd col). First src = high.
__device__ __forceinline__ unsigned bfpack(float a, float b) {
    unsigned u;
    asm("cvt.rn.bf16x2.f32 %0, %1, %2;" : "=r"(u) : "f"(b), "f"(a));
    return u;
}

// ---------------- persistent main kernel ------------------------------------
extern "C" __global__ void __launch_bounds__(NTHR, 1)
crf_main(const float* __restrict__ h, const float* __restrict__ trans,
         float* __restrict__ out, int S) {
    __shared__ float2 part2[8 * NTHR];   // 16 KB reduction scratch
    __shared__ float  s_rmax[ROWS];
    __shared__ float  s_Vcur;

    const int b = blockIdx.x, t = threadIdx.x;
    const int lane = t & 31, w = t >> 5;
    const int row0 = b * ROWS;
    const int c0 = 8 * t;                // this thread's 8 columns
    const unsigned nb = gridDim.x;

    // ---- prologue: build E = exp(trans - rowmax) in REGISTERS (f32) --------
    float E[ROWS][8];
    {
        float lm[ROWS];
        #pragma unroll
        for (int r = 0; r < ROWS; r++) {
            const float4* tp = (const float4*)(trans + (size_t)(row0 + r) * TAGS + c0);
            float4 a = __ldg(tp), bb = __ldg(tp + 1);
            E[r][0] = a.x;  E[r][1] = a.y;  E[r][2] = a.z;  E[r][3] = a.w;
            E[r][4] = bb.x; E[r][5] = bb.y; E[r][6] = bb.z; E[r][7] = bb.w;
            lm[r] = fmaxf(fmaxf(fmaxf(a.x, a.y), fmaxf(a.z, a.w)),
                          fmaxf(fmaxf(bb.x, bb.y), fmaxf(bb.z, bb.w)));
        }
        #pragma unroll
        for (int pr = 0; pr < 8; pr++)
            part2[pr * NTHR + t] = make_float2(lm[2 * pr], lm[2 * pr + 1]);
        __syncthreads();
        float2 m = make_float2(-3.4e38f, -3.4e38f);
        for (int i = lane; i < NTHR; i += 32) {
            float2 v = part2[w * NTHR + i];
            m.x = fmaxf(m.x, v.x); m.y = fmaxf(m.y, v.y);
        }
        #pragma unroll
        for (int o = 16; o; o >>= 1) {
            m.x = fmaxf(m.x, __shfl_xor_sync(~0u, m.x, o));
            m.y = fmaxf(m.y, __shfl_xor_sync(~0u, m.y, o));
        }
        if (lane == 0) { s_rmax[2 * w] = m.x; s_rmax[2 * w + 1] = m.y; }
        if (t == 0) s_Vcur = 0.0f;
        __syncthreads();
        #pragma unroll
        for (int r = 0; r < ROWS; r++) {
            float rm = s_rmax[r];
            #pragma unroll
            for (int q = 0; q < 8; q++)
                E[r][q] = __expf(E[r][q] - rm);
        }
    }
    const float2 myrmax = make_float2(s_rmax[2 * w], s_rmax[2 * w + 1]);

    // emit prefetch for step 0 (lane0 of warp w owns rows 2w, 2w+1)
    float2 emit = make_float2(0.f, 0.f);
    if (lane == 0) emit = __ldg((const float2*)(h + row0 + 2 * w));
    __syncthreads();

    float Vprev = 0.0f;    // sigma used by producers of the CURRENT step's p

    // ---- main sequential scan ----
    for (int s = 0; s < S; s++) {
        // t0: fetch this step's V (published with p, gated by same barrier);
        // consumed only after reduction -> fully overlapped with GEMV
        float vld = 0.0f;
        if (t == 0) vld = __ldcg(&g_V[s & 1][(b >> 4) * 32]);

        // prefetch next step's emissions
        float2 emitN = emit;
        if (lane == 0 && s + 1 < S)
            emitN = __ldg((const float2*)(h + (size_t)(s + 1) * TAGS + row0 + 2 * w));

        // load own 8 p values (bf16 pairs, 16B) -- no exp needed
        uint4 pw;
        asm volatile("ld.global.cg.v4.u32 {%0,%1,%2,%3},[%4];"
                     : "=r"(pw.x), "=r"(pw.y), "=r"(pw.z), "=r"(pw.w)
                     : "l"((const uint4*)(g_p[s & 1]) + t) : "memory");
        float p[8];
        p[0] = bflo(pw.x); p[1] = bfhi(pw.x);
        p[2] = bflo(pw.y); p[3] = bfhi(pw.y);
        p[4] = bflo(pw.z); p[5] = bfhi(pw.z);
        p[6] = bflo(pw.w); p[7] = bfhi(pw.w);

        // register GEMV: 16 rows x 8 cols, scalar FFMA
        float sv[ROWS];
        #pragma unroll
        for (int r = 0; r < ROWS; r++) {
            float a0 = E[r][0] * p[0];
            float a1 = E[r][1] * p[1];
            a0 = fmaf(E[r][2], p[2], a0);
            a1 = fmaf(E[r][3], p[3], a1);
            a0 = fmaf(E[r][4], p[4], a0);
            a1 = fmaf(E[r][5], p[5], a1);
            a0 = fmaf(E[r][6], p[6], a0);
            a1 = fmaf(E[r][7], p[7], a1);
            sv[r] = a0 + a1;
        }
        #pragma unroll
        for (int pr = 0; pr < 8; pr++)
            part2[pr * NTHR + t] = make_float2(sv[2 * pr], sv[2 * pr + 1]);
        if (t == 0) s_Vcur = vld;
        __syncthreads();                                   // #1

        // warp w reduces row pair (2w, 2w+1) over all 256 thread-partials
        float2 acc = make_float2(0.f, 0.f);
        #pragma unroll
        for (int i = 0; i < NTHR / 32; i++) {
            float2 v = part2[w * NTHR + lane + 32 * i];
            acc.x += v.x; acc.y += v.y;
        }
        #pragma unroll
        for (int o = 16; o; o >>= 1) {
            acc.x += __shfl_xor_sync(~0u, acc.x, o);
            acc.y += __shfl_xor_sync(~0u, acc.y, o);
        }
        const float Vcur = s_Vcur;            // V_s (safe: after sync #1)
        if (lane == 0) {
            // fv_{s+1} rows (2w, 2w+1); sigma_s = Vprev
            float2 nf;
            nf.x = __logf(acc.x) + Vprev + myrmax.x + emit.x;
            nf.y = __logf(acc.y) + Vprev + myrmax.y + emit.y;
            // publish p_{s+1} = exp(fv - V_s) as bf16 pair (one u32 store)
            unsigned pk = bfpack(__expf(nf.x - Vcur), __expf(nf.y - Vcur));
            *(g_p[(s + 1) & 1] + row0 / 2 + w) = pk;
            if (b == 0 && w == 0) {           // publish V_{s+1} = fv_{s+1}[1], x8 replicas
                #pragma unroll
                for (int rep = 0; rep < 8; rep++)
                    g_V[(s + 1) & 1][rep * 32] = nf.y;
            }
            __threadfence();                  // release p (+V) before barrier arrive
        }
        emit = emitN;
        Vprev = Vcur;                         // all threads track sigma chain
        __syncthreads();                                   // #2
        if (t == 0) {
            atomicAdd(&g_bar, 1u);
            const unsigned target = (unsigned)(s + 1) * nb;
            while (*((volatile unsigned*)&g_bar) < target) { }
            __threadfence();                  // acquire before next step's reads
        }
        __syncthreads();                                   // #3
    }

    // ---- final: logsumexp(fv_S + trans[END=1, :]) on CTA 0 ----
    // fv_S[j] = log(p_S[j]) + V_{S-1};  Vprev now holds V_{S-1}
    if (b == 0) {
        const float* trow = trans + TAGS;         // row END_IDX = 1
        float* sp = (float*)part2;                // 16 KB scratch >= 8 KB needed
        float lm = -3.4e38f;
        #pragma unroll
        for (int k = 0; k < (TAGS / 2) / NTHR; k++) {
            int j = t + NTHR * k;                 // u32 index: cols 2j, 2j+1
            unsigned u;
            asm volatile("ld.global.cg.u32 %0,[%1];" : "=r"(u)
                         : "l"(g_p[S & 1] + j) : "memory");
            float fa = __logf(bflo(u)) + Vprev + __ldg(trow + 2 * j);
            float fb = __logf(bfhi(u)) + Vprev + __ldg(trow + 2 * j + 1);
            sp[2 * j]     = fa;
            sp[2 * j + 1] = fb;
            lm = fmaxf(lm, fmaxf(fa, fb));
        }
        #pragma unroll
        for (int o = 16; o; o >>= 1) lm = fmaxf(lm, __shfl_xor_sync(~0u, lm, o));
        if (lane == 0) s_rmax[w] = lm;
        __syncthreads();
        float M = s_rmax[0];
        #pragma unroll
        for (int q = 1; q < 8; q++) M = fmaxf(M, s_rmax[q]);
        float sum = 0.f;
        #pragma unroll
        for (int k = 0; k < TAGS / NTHR; k++)
            sum += __expf(sp[t + NTHR * k] - M);
        #pragma unroll
        for (int o = 16; o; o >>= 1) sum += __shfl_xor_sync(~0u, sum, o);
        __syncthreads();
        if (lane == 0) s_rmax[w] = sum;
        __syncthreads();
        if (t == 0) {
            float tot = 0.f;
            #pragma unroll
            for (int q = 0; q < 8; q++) tot += s_rmax[q];
            out[0] = __logf(tot) + M;
        }
    }
}

// ---------------- launch ----------------------------------------------------
extern "C" void kernel_launch(void* const* d_in, const int* in_sizes, int n_in,
                              void* d_out, int out_size) {
    const float* h     = (const float*)d_in[0];
    const float* trans = (const float*)d_in[1];
    float* out = (float*)d_out;
    const int S = in_sizes[0] / TAGS;

    init_kernel<<<(TAGS + 255) / 256, 256>>>();
    crf_main<<<NCTA, NTHR>>>(h, trans, out, S);
}

// round 15
// speedup vs baseline: 1.0110x; 1.0110x over previous
#include <cuda_runtime.h>
#include <cstdint>

#define TAGS 2048
#define NCTA 128
#define ROWS 16          // NCTA*ROWS == TAGS
#define NTHR 256
#define NEGV -10000.0f

// ---------------- persistent device state ----------------
__device__ float    g_fv[2][TAGS];        // double-buffered forward variable
__device__ unsigned g_bar;                // grid barrier counter (R3-proven)

__global__ void init_kernel() {
    int j = blockIdx.x * blockDim.x + threadIdx.x;
    if (j < TAGS) g_fv[0][j] = (j == 0) ? 0.0f : NEGV;
    if (j == 0) g_bar = 0u;
}

__device__ __forceinline__ void fence_acqrel_gpu() {
    asm volatile("fence.acq_rel.gpu;" ::: "memory");
}

// ---------------- persistent main kernel ------------------------------------
extern "C" __global__ void __launch_bounds__(NTHR, 1)
crf_main(const float* __restrict__ h, const float* __restrict__ trans,
         float* __restrict__ out, int S) {
    __shared__ float2 part2[8 * NTHR];   // 16 KB reduction scratch
    __shared__ float  s_rmax[ROWS];
    __shared__ float  s_shift;

    const int b = blockIdx.x, t = threadIdx.x;
    const int lane = t & 31, w = t >> 5;
    const int row0 = b * ROWS;
    const int c0 = 8 * t;                // this thread's 8 columns
    const unsigned nb = gridDim.x;

    // ---- prologue: build E = exp(trans - rowmax) in REGISTERS (f32) --------
    float E[ROWS][8];
    {
        float lm[ROWS];
        #pragma unroll
        for (int r = 0; r < ROWS; r++) {
            const float4* tp = (const float4*)(trans + (size_t)(row0 + r) * TAGS + c0);
            float4 a = __ldg(tp), bb = __ldg(tp + 1);
            E[r][0] = a.x;  E[r][1] = a.y;  E[r][2] = a.z;  E[r][3] = a.w;
            E[r][4] = bb.x; E[r][5] = bb.y; E[r][6] = bb.z; E[r][7] = bb.w;
            lm[r] = fmaxf(fmaxf(fmaxf(a.x, a.y), fmaxf(a.z, a.w)),
                          fmaxf(fmaxf(bb.x, bb.y), fmaxf(bb.z, bb.w)));
        }
        #pragma unroll
        for (int pr = 0; pr < 8; pr++)
            part2[pr * NTHR + t] = make_float2(lm[2 * pr], lm[2 * pr + 1]);
        __syncthreads();
        float2 m = make_float2(-3.4e38f, -3.4e38f);
        for (int i = lane; i < NTHR; i += 32) {
            float2 v = part2[w * NTHR + i];
            m.x = fmaxf(m.x, v.x); m.y = fmaxf(m.y, v.y);
        }
        #pragma unroll
        for (int o = 16; o; o >>= 1) {
            m.x = fmaxf(m.x, __shfl_xor_sync(~0u, m.x, o));
            m.y = fmaxf(m.y, __shfl_xor_sync(~0u, m.y, o));
        }
        if (lane == 0) { s_rmax[2 * w] = m.x; s_rmax[2 * w + 1] = m.y; }
        if (t == 0) s_shift = 0.0f;
        __syncthreads();
        #pragma unroll
        for (int r = 0; r < ROWS; r++) {
            float rm = s_rmax[r];
            #pragma unroll
            for (int q = 0; q < 8; q++)
                E[r][q] = __expf(E[r][q] - rm);
        }
    }
    const float2 myrmax = make_float2(s_rmax[2 * w], s_rmax[2 * w + 1]);

    // emit prefetch for step 0 (lane0 of warp w owns rows 2w, 2w+1)
    float2 emit = make_float2(0.f, 0.f);
    if (lane == 0) emit = __ldg((const float2*)(h + row0 + 2 * w));
    __syncthreads();

    // ---- main sequential scan ----
    for (int s = 0; s < S; s++) {
        const float shift = s_shift;          // per-CTA local shift; cancels exactly
        const float* fvr = g_fv[s & 1];

        // prefetch next step's emissions
        float2 emitN = emit;
        if (lane == 0 && s + 1 < S)
            emitN = __ldg((const float2*)(h + (size_t)(s + 1) * TAGS + row0 + 2 * w));

        // p = exp(fv - shift), own 8 entries, L1-bypassing (written by peer SMs)
        float4 f0 = __ldcg((const float4*)(fvr + c0));
        float4 f1 = __ldcg((const float4*)(fvr + c0) + 1);
        float p[8];
        p[0] = __expf(f0.x - shift); p[1] = __expf(f0.y - shift);
        p[2] = __expf(f0.z - shift); p[3] = __expf(f0.w - shift);
        p[4] = __expf(f1.x - shift); p[5] = __expf(f1.y - shift);
        p[6] = __expf(f1.z - shift); p[7] = __expf(f1.w - shift);

        // register GEMV: 16 rows x 8 cols, scalar FFMA
        float sv[ROWS];
        #pragma unroll
        for (int r = 0; r < ROWS; r++) {
            float a0 = E[r][0] * p[0];
            float a1 = E[r][1] * p[1];
            a0 = fmaf(E[r][2], p[2], a0);
            a1 = fmaf(E[r][3], p[3], a1);
            a0 = fmaf(E[r][4], p[4], a0);
            a1 = fmaf(E[r][5], p[5], a1);
            a0 = fmaf(E[r][6], p[6], a0);
            a1 = fmaf(E[r][7], p[7], a1);
            sv[r] = a0 + a1;
        }
        #pragma unroll
        for (int pr = 0; pr < 8; pr++)
            part2[pr * NTHR + t] = make_float2(sv[2 * pr], sv[2 * pr + 1]);
        __syncthreads();                                   // #1

        // warp w reduces row pair (2w, 2w+1) over all 256 thread-partials
        float2 acc = make_float2(0.f, 0.f);
        #pragma unroll
        for (int i = 0; i < NTHR / 32; i++) {
            float2 v = part2[w * NTHR + lane + 32 * i];
            acc.x += v.x; acc.y += v.y;
        }
        #pragma unroll
        for (int o = 16; o; o >>= 1) {
            acc.x += __shfl_xor_sync(~0u, acc.x, o);
            acc.y += __shfl_xor_sync(~0u, acc.y, o);
        }
        if (lane == 0) {
            float2 nf;
            nf.x = __logf(acc.x) + shift + myrmax.x + emit.x;
            nf.y = __logf(acc.y) + shift + myrmax.y + emit.y;
            if (w == 0) s_shift = nf.y;   // next shift: local value (no L2 re-read)
            *(float2*)(g_fv[(s + 1) & 1] + row0 + 2 * w) = nf;
            // NO per-warp fence: cumulativity via sync #2 + t0's single gpu fence
        }
        emit = emitN;
        __syncthreads();                                   // #2 (cta-scope acq_rel)
        if (t == 0) {
            fence_acqrel_gpu();           // cumulative: orders ALL warps' fv stores
            atomicAdd(&g_bar, 1u);
            const unsigned target = (unsigned)(s + 1) * nb;
            while (*((volatile unsigned*)&g_bar) < target) { }
            fence_acqrel_gpu();           // acquire; propagated via sync #3
        }
        __syncthreads();                                   // #3
    }

    // ---- final: logsumexp(fv + trans[END=1, :]) on CTA 0 ----
    if (b == 0) {
        const float* fvf  = g_fv[S & 1];
        const float* trow = trans + TAGS;         // row END_IDX = 1
        float* sp = (float*)part2;                // 16 KB scratch >= 8 KB needed
        float lm = -3.4e38f;
        #pragma unroll
        for (int k = 0; k < TAGS / NTHR; k++) {
            int j = t + NTHR * k;
            float v = __ldcg(fvf + j) + __ldg(trow + j);
            sp[j] = v;
            lm = fmaxf(lm, v);
        }
        #pragma unroll
        for (int o = 16; o; o >>= 1) lm = fmaxf(lm, __shfl_xor_sync(~0u, lm, o));
        if (lane == 0) s_rmax[w] = lm;
        __syncthreads();
        float M = s_rmax[0];
        #pragma unroll
        for (int q = 1; q < 8; q++) M = fmaxf(M, s_rmax[q]);
        float sum = 0.f;
        #pragma unroll
        for (int k = 0; k < TAGS / NTHR; k++)
            sum += __expf(sp[t + NTHR * k] - M);
        #pragma unroll
        for (int o = 16; o; o >>= 1) sum += __shfl_xor_sync(~0u, sum, o);
        __syncthreads();
        if (lane == 0) s_rmax[w] = sum;
        __syncthreads();
        if (t == 0) {
            float tot = 0.f;
            #pragma unroll
            for (int q = 0; q < 8; q++) tot += s_rmax[q];
            out[0] = __logf(tot) + M;
        }
    }
}

// ---------------- launch ----------------------------------------------------
extern "C" void kernel_launch(void* const* d_in, const int* in_sizes, int n_in,
                              void* d_out, int out_size) {
    const float* h     = (const float*)d_in[0];
    const float* trans = (const float*)d_in[1];
    float* out = (float*)d_out;
    const int S = in_sizes[0] / TAGS;

    init_kernel<<<(TAGS + 255) / 256, 256>>>();
    crf_main<<<NCTA, NTHR>>>(h, trans, out, S);
}